// round 1
// baseline (speedup 1.0000x reference)
#include <cuda_runtime.h>
#include <math.h>

#define B_  32
#define LQ  512
#define LS  1024
#define DD  1024
#define SS  256
#define EPSF 1e-8f

// Scratch (no allocation allowed): 64 MB each.
__device__ float g_attn[B_ * LS * LQ];   // (b, s, q)
__device__ float g_wc  [B_ * LQ * DD];   // (b, q, d) -> later holds diff^2

#define BM 128
#define BN 64
#define BK 16

__device__ __forceinline__ float lrelu(float x) {
    return x > 0.f ? x : 0.1f * x;
}

// ---------------------------------------------------------------------------
// GEMM1 (NT): attn[b,s,q] = leaky_relu( sum_d ctx[b,s,d] * qry[b,q,d]*mat[b,q,d] )
// ---------------------------------------------------------------------------
__global__ __launch_bounds__(256) void gemm1_kernel(
    const float* __restrict__ ctx,
    const float* __restrict__ qry,
    const float* __restrict__ mat)
{
    __shared__ float As[BK][BM];   // s-major tile, transposed: [k][m]
    __shared__ float Bs[BK][BN];   // q tile (query*matrix), transposed: [k][n]

    const int b  = blockIdx.z;
    const int s0 = blockIdx.y * BM;
    const int q0 = blockIdx.x * BN;

    const float* A = ctx + (size_t)b * LS * DD;
    const float* Q = qry + (size_t)b * LQ * DD;
    const float* M = mat + (size_t)b * LQ * DD;

    const int tid = threadIdx.x;
    const int lr  = tid >> 2;          // 0..63
    const int lc  = (tid & 3) << 2;    // 0,4,8,12

    float4 a0, a1, bq;
    // prefetch k0 = 0
    a0 = *(const float4*)(A + (size_t)(s0 + lr)      * DD + lc);
    a1 = *(const float4*)(A + (size_t)(s0 + lr + 64) * DD + lc);
    {
        float4 qv = *(const float4*)(Q + (size_t)(q0 + lr) * DD + lc);
        float4 mv = *(const float4*)(M + (size_t)(q0 + lr) * DD + lc);
        bq = make_float4(qv.x * mv.x, qv.y * mv.y, qv.z * mv.z, qv.w * mv.w);
    }

    float acc[8][4];
#pragma unroll
    for (int i = 0; i < 8; i++)
#pragma unroll
        for (int j = 0; j < 4; j++) acc[i][j] = 0.f;

    const int ty = tid >> 4;   // 0..15
    const int tx = tid & 15;   // 0..15

    for (int k0 = 0; k0 < DD; k0 += BK) {
        As[lc + 0][lr]      = a0.x; As[lc + 1][lr]      = a0.y;
        As[lc + 2][lr]      = a0.z; As[lc + 3][lr]      = a0.w;
        As[lc + 0][lr + 64] = a1.x; As[lc + 1][lr + 64] = a1.y;
        As[lc + 2][lr + 64] = a1.z; As[lc + 3][lr + 64] = a1.w;
        Bs[lc + 0][lr] = bq.x; Bs[lc + 1][lr] = bq.y;
        Bs[lc + 2][lr] = bq.z; Bs[lc + 3][lr] = bq.w;
        __syncthreads();

        const int kn = k0 + BK;
        if (kn < DD) {
            a0 = *(const float4*)(A + (size_t)(s0 + lr)      * DD + kn + lc);
            a1 = *(const float4*)(A + (size_t)(s0 + lr + 64) * DD + kn + lc);
            float4 qv = *(const float4*)(Q + (size_t)(q0 + lr) * DD + kn + lc);
            float4 mv = *(const float4*)(M + (size_t)(q0 + lr) * DD + kn + lc);
            bq = make_float4(qv.x * mv.x, qv.y * mv.y, qv.z * mv.z, qv.w * mv.w);
        }

#pragma unroll
        for (int kk = 0; kk < BK; kk++) {
            float a[8], bb[4];
            *(float4*)&a[0] = *(const float4*)&As[kk][ty * 8];
            *(float4*)&a[4] = *(const float4*)&As[kk][ty * 8 + 4];
            *(float4*)&bb[0] = *(const float4*)&Bs[kk][tx * 4];
#pragma unroll
            for (int i = 0; i < 8; i++)
#pragma unroll
                for (int j = 0; j < 4; j++)
                    acc[i][j] = fmaf(a[i], bb[j], acc[i][j]);
        }
        __syncthreads();
    }

    float* out = g_attn + (size_t)b * LS * LQ;
#pragma unroll
    for (int i = 0; i < 8; i++) {
        const int s = s0 + ty * 8 + i;
        float4 v;
        v.x = lrelu(acc[i][0]); v.y = lrelu(acc[i][1]);
        v.z = lrelu(acc[i][2]); v.w = lrelu(acc[i][3]);
        *(float4*)(out + (size_t)s * LQ + q0 + tx * 4) = v;
    }
}

// ---------------------------------------------------------------------------
// Row l2-normalize attn over q (axis Lq), per (b, s) row. 1 warp per row.
// ---------------------------------------------------------------------------
__global__ __launch_bounds__(256) void rownorm_attn_kernel()
{
    const int warp = threadIdx.x >> 5;
    const int lane = threadIdx.x & 31;
    const size_t row = (size_t)blockIdx.x * 8 + warp;   // b*LS + s
    float* p = g_attn + row * LQ;

    float sum = 0.f;
#pragma unroll 4
    for (int i = lane; i < LQ; i += 32) {
        float v = p[i];
        sum += v * v;
    }
#pragma unroll
    for (int o = 16; o > 0; o >>= 1)
        sum += __shfl_xor_sync(0xffffffffu, sum, o);

    const float inv = 1.f / (sqrtf(sum) + EPSF);
#pragma unroll 4
    for (int i = lane; i < LQ; i += 32)
        p[i] *= inv;
}

// ---------------------------------------------------------------------------
// Softmax over s (columns of the (Ls, Lq) layout). One thread per (b, q).
// ---------------------------------------------------------------------------
__global__ __launch_bounds__(128) void softmax_kernel(const int* __restrict__ smooth_ptr)
{
    // smooth might arrive as int32 or float32 bits; disambiguate.
    float sm;
    {
        int iv = *smooth_ptr;
        if (iv >= -1000000 && iv <= 1000000) sm = (float)iv;
        else                                  sm = __int_as_float(iv);
    }

    const int b = blockIdx.x >> 2;
    const int q = ((blockIdx.x & 3) << 7) + threadIdx.x;
    float* base = g_attn + (size_t)b * LS * LQ + q;

    float m = -1e30f, l = 0.f;
    for (int s = 0; s < LS; s++) {
        float v = base[(size_t)s * LQ] * sm;
        float mn = fmaxf(m, v);
        l = l * __expf(m - mn) + __expf(v - mn);
        m = mn;
    }
    const float invl = 1.f / l;
    for (int s = 0; s < LS; s++) {
        float v = base[(size_t)s * LQ] * sm;
        base[(size_t)s * LQ] = __expf(v - m) * invl;
    }
}

// ---------------------------------------------------------------------------
// GEMM2 (TN): wc[b,q,d] = sum_s attn[b,s,q] * ctx[b,s,d]
// ---------------------------------------------------------------------------
__global__ __launch_bounds__(256) void gemm2_kernel(const float* __restrict__ ctx)
{
    __shared__ float As[BK][BM];   // attn tile: [k=s][m=q], loaded directly
    __shared__ float Bs[BK][BN];   // ctx tile:  [k=s][n=d], loaded directly

    const int b  = blockIdx.z;
    const int q0 = blockIdx.y * BM;
    const int d0 = blockIdx.x * BN;

    const float* A = g_attn + (size_t)b * LS * LQ;
    const float* C = ctx    + (size_t)b * LS * DD;

    const int tid = threadIdx.x;
    const int ar  = tid >> 5;          // 0..7
    const int ac  = (tid & 31) << 2;   // 0..124
    const int br  = tid >> 4;          // 0..15
    const int bc  = (tid & 15) << 2;   // 0..60

    float4 va0, va1, vb;
    va0 = *(const float4*)(A + (size_t)(ar)     * LQ + q0 + ac);
    va1 = *(const float4*)(A + (size_t)(ar + 8) * LQ + q0 + ac);
    vb  = *(const float4*)(C + (size_t)(br)     * DD + d0 + bc);

    float acc[8][4];
#pragma unroll
    for (int i = 0; i < 8; i++)
#pragma unroll
        for (int j = 0; j < 4; j++) acc[i][j] = 0.f;

    const int ty = tid >> 4;
    const int tx = tid & 15;

    for (int k0 = 0; k0 < LS; k0 += BK) {
        *(float4*)&As[ar][ac]     = va0;
        *(float4*)&As[ar + 8][ac] = va1;
        *(float4*)&Bs[br][bc]     = vb;
        __syncthreads();

        const int kn = k0 + BK;
        if (kn < LS) {
            va0 = *(const float4*)(A + (size_t)(kn + ar)     * LQ + q0 + ac);
            va1 = *(const float4*)(A + (size_t)(kn + ar + 8) * LQ + q0 + ac);
            vb  = *(const float4*)(C + (size_t)(kn + br)     * DD + d0 + bc);
        }

#pragma unroll
        for (int kk = 0; kk < BK; kk++) {
            float a[8], bb[4];
            *(float4*)&a[0] = *(const float4*)&As[kk][ty * 8];
            *(float4*)&a[4] = *(const float4*)&As[kk][ty * 8 + 4];
            *(float4*)&bb[0] = *(const float4*)&Bs[kk][tx * 4];
#pragma unroll
            for (int i = 0; i < 8; i++)
#pragma unroll
                for (int j = 0; j < 4; j++)
                    acc[i][j] = fmaf(a[i], bb[j], acc[i][j]);
        }
        __syncthreads();
    }

    float* out = g_wc + (size_t)b * LQ * DD;
#pragma unroll
    for (int i = 0; i < 8; i++) {
        const int q = q0 + ty * 8 + i;
        float4 v;
        v.x = acc[i][0]; v.y = acc[i][1]; v.z = acc[i][2]; v.w = acc[i][3];
        *(float4*)(out + (size_t)q * DD + d0 + tx * 4) = v;
    }
}

// ---------------------------------------------------------------------------
// diff2: wc row -> l2norm over D, then (query - wc_norm)^2, in place.
// One block per (b, q) row.
// ---------------------------------------------------------------------------
__global__ __launch_bounds__(256) void diff2_kernel(const float* __restrict__ qry)
{
    __shared__ float red[256];
    const size_t row = blockIdx.x;                 // b*LQ + q
    float* wc = g_wc + row * DD;
    const float* qp = qry + row * DD;
    const int tid = threadIdx.x;

    float v[4];
    float s = 0.f;
#pragma unroll
    for (int i = 0; i < 4; i++) {
        v[i] = wc[tid + i * 256];
        s += v[i] * v[i];
    }
    red[tid] = s;
    __syncthreads();
    for (int o = 128; o > 0; o >>= 1) {
        if (tid < o) red[tid] += red[tid + o];
        __syncthreads();
    }
    const float inv = 1.f / (sqrtf(red[0]) + EPSF);
#pragma unroll
    for (int i = 0; i < 4; i++) {
        float d = qp[tid + i * 256] - v[i] * inv;
        wc[tid + i * 256] = d * d;
    }
}

// ---------------------------------------------------------------------------
// GEMM3 (NT): out[b,q,s] = sum_d diff2[b,q,d] * W[s,d] + bias[s]
// ---------------------------------------------------------------------------
__global__ __launch_bounds__(256) void gemm3_kernel(
    const float* __restrict__ W,
    const float* __restrict__ bias,
    float* __restrict__ outp)
{
    __shared__ float As[BK][BM];
    __shared__ float Bs[BK][BN];

    const int b  = blockIdx.z;
    const int q0 = blockIdx.y * BM;
    const int n0 = blockIdx.x * BN;

    const float* A = g_wc + (size_t)b * LQ * DD;

    const int tid = threadIdx.x;
    const int lr  = tid >> 2;
    const int lc  = (tid & 3) << 2;

    float4 a0, a1, bw;
    a0 = *(const float4*)(A + (size_t)(q0 + lr)      * DD + lc);
    a1 = *(const float4*)(A + (size_t)(q0 + lr + 64) * DD + lc);
    bw = *(const float4*)(W + (size_t)(n0 + lr) * DD + lc);

    float acc[8][4];
#pragma unroll
    for (int i = 0; i < 8; i++)
#pragma unroll
        for (int j = 0; j < 4; j++) acc[i][j] = 0.f;

    const int ty = tid >> 4;
    const int tx = tid & 15;

    for (int k0 = 0; k0 < DD; k0 += BK) {
        As[lc + 0][lr]      = a0.x; As[lc + 1][lr]      = a0.y;
        As[lc + 2][lr]      = a0.z; As[lc + 3][lr]      = a0.w;
        As[lc + 0][lr + 64] = a1.x; As[lc + 1][lr + 64] = a1.y;
        As[lc + 2][lr + 64] = a1.z; As[lc + 3][lr + 64] = a1.w;
        Bs[lc + 0][lr] = bw.x; Bs[lc + 1][lr] = bw.y;
        Bs[lc + 2][lr] = bw.z; Bs[lc + 3][lr] = bw.w;
        __syncthreads();

        const int kn = k0 + BK;
        if (kn < DD) {
            a0 = *(const float4*)(A + (size_t)(q0 + lr)      * DD + kn + lc);
            a1 = *(const float4*)(A + (size_t)(q0 + lr + 64) * DD + kn + lc);
            bw = *(const float4*)(W + (size_t)(n0 + lr) * DD + kn + lc);
        }

#pragma unroll
        for (int kk = 0; kk < BK; kk++) {
            float a[8], bb[4];
            *(float4*)&a[0] = *(const float4*)&As[kk][ty * 8];
            *(float4*)&a[4] = *(const float4*)&As[kk][ty * 8 + 4];
            *(float4*)&bb[0] = *(const float4*)&Bs[kk][tx * 4];
#pragma unroll
            for (int i = 0; i < 8; i++)
#pragma unroll
                for (int j = 0; j < 4; j++)
                    acc[i][j] = fmaf(a[i], bb[j], acc[i][j]);
        }
        __syncthreads();
    }

    float4 bv = *(const float4*)(bias + n0 + tx * 4);
#pragma unroll
    for (int i = 0; i < 8; i++) {
        const int q = q0 + ty * 8 + i;
        float4 v;
        v.x = acc[i][0] + bv.x; v.y = acc[i][1] + bv.y;
        v.z = acc[i][2] + bv.z; v.w = acc[i][3] + bv.w;
        *(float4*)(outp + (size_t)b * LQ * SS + (size_t)q * SS + n0 + tx * 4) = v;
    }
}

// ---------------------------------------------------------------------------
// Final l2-normalize over S, in place on d_out. One block (256 thr) per row.
// ---------------------------------------------------------------------------
__global__ __launch_bounds__(256) void outnorm_kernel(float* __restrict__ outp)
{
    __shared__ float red[256];
    const size_t row = blockIdx.x;      // b*LQ + q
    float* p = outp + row * SS;
    const int tid = threadIdx.x;

    const float v = p[tid];
    red[tid] = v * v;
    __syncthreads();
    for (int o = 128; o > 0; o >>= 1) {
        if (tid < o) red[tid] += red[tid + o];
        __syncthreads();
    }
    const float inv = 1.f / (sqrtf(red[0]) + EPSF);
    p[tid] = v * inv;
}

// ---------------------------------------------------------------------------
extern "C" void kernel_launch(void* const* d_in, const int* in_sizes, int n_in,
                              void* d_out, int out_size)
{
    const float* qry  = (const float*)d_in[0];   // (B, Lq, D)
    const float* ctx  = (const float*)d_in[1];   // (B, Ls, D)
    const float* mat  = (const float*)d_in[2];   // (B, Lq, D)
    const float* W    = (const float*)d_in[3];   // (S, D)
    const float* bias = (const float*)d_in[4];   // (S,)
    const int*   smp  = (const int*)d_in[5];     // smooth scalar
    float* outp = (float*)d_out;

    // 1. attn = leaky_relu(ctx @ (qry*mat)^T)
    gemm1_kernel<<<dim3(LQ / BN, LS / BM, B_), 256>>>(ctx, qry, mat);
    // 2. l2 normalize rows (over q)
    rownorm_attn_kernel<<<(B_ * LS) / 8, 256>>>();
    // 3. softmax over s per (b, q) column
    softmax_kernel<<<B_ * (LQ / 128), 128>>>(smp);
    // 4. wcontext = attn^T @ ctx
    gemm2_kernel<<<dim3(DD / BN, LQ / BM, B_), 256>>>(ctx);
    // 5. l2norm wcontext + squared diff, in place
    diff2_kernel<<<B_ * LQ, 256>>>(qry);
    // 6. sim = diff2 @ W^T + b
    gemm3_kernel<<<dim3(SS / BN, LQ / BM, B_), 256>>>(W, bias, outp);
    // 7. final l2 normalize over S
    outnorm_kernel<<<B_ * LQ, 256>>>(outp);
}

// round 3
// speedup vs baseline: 2.4407x; 2.4407x over previous
#include <cuda_runtime.h>
#include <cstdint>
#include <math.h>

#define B_  32
#define LQ  512
#define LS  1024
#define DD  1024
#define SS  256
#define EPSF 1e-8f

// Scratch (allocation forbidden): device globals.
__device__ float g_qm  [B_ * LQ * DD];   // rna(query*matrix)       64MB
__device__ float g_ctxR[B_ * LS * DD];   // rna(ctx)               128MB
__device__ float g_ctxT[B_ * DD * LS];   // rna(ctx^T)             128MB
__device__ float g_attn[B_ * LQ * LS];   // attn (b, q, s)          64MB
__device__ float g_wc  [B_ * LQ * DD];   // wcontext -> diff^2      64MB
__device__ float g_w   [SS * DD];        // rna(W)                   1MB

// ---------------------------------------------------------------------------
__device__ __forceinline__ uint32_t smem_u32(const void* p) {
    uint32_t a;
    asm("{ .reg .u64 t; cvta.to.shared.u64 t, %1; cvt.u32.u64 %0, t; }"
        : "=r"(a) : "l"(p));
    return a;
}
__device__ __forceinline__ float frna(float x) {
    uint32_t u;
    asm("cvt.rna.tf32.f32 %0, %1;" : "=r"(u) : "f"(x));
    return __uint_as_float(u);
}
__device__ __forceinline__ float lrelu(float x) { return x > 0.f ? x : 0.1f * x; }

__device__ __forceinline__ void cp16(uint32_t s, const void* g) {
    asm volatile("cp.async.cg.shared.global [%0], [%1], 16;" :: "r"(s), "l"(g));
}
__device__ __forceinline__ void cp_commit() {
    asm volatile("cp.async.commit_group;" ::: "memory");
}
template <int N> __device__ __forceinline__ void cp_wait() {
    asm volatile("cp.async.wait_group %0;" :: "n"(N) : "memory");
}

// mma.sync m16n8k8 tf32 (baseline PTX, works on sm_103 non-'a' target)
__device__ __forceinline__ void mma8(float* c, const uint32_t* a, const uint32_t* b) {
    asm volatile(
        "mma.sync.aligned.m16n8k8.row.col.f32.tf32.tf32.f32 "
        "{%0,%1,%2,%3}, {%4,%5,%6,%7}, {%8,%9}, {%0,%1,%2,%3};"
        : "+f"(c[0]), "+f"(c[1]), "+f"(c[2]), "+f"(c[3])
        : "r"(a[0]), "r"(a[1]), "r"(a[2]), "r"(a[3]), "r"(b[0]), "r"(b[1]));
}

// ---------------------------------------------------------------------------
// tf32 warp-MMA GEMM: D[m,n] = sum_k A[m,k] * B[n,k]   (K = 1024, K-major)
//   EPI 0: leaky_relu            (attn)
//   EPI 1: raw                   (wcontext)
//   EPI 2: +bias, l2norm over the 256-wide N (out), block tile 64x256
// ---------------------------------------------------------------------------
#define KTOT 1024
#define BKC  32
#define NIT  (KTOT / BKC)
#define LDS_ 36     // padded row length in floats (conflict-free fragments)

template <int EPI>
__global__ __launch_bounds__(256, 1) void mma_gemm(
    const float* __restrict__ gA, const float* __restrict__ gB,
    float* __restrict__ gD, const float* __restrict__ bias,
    int lda, int ldb, int ldd, size_t sA, size_t sB, size_t sD)
{
    constexpr int TBM = (EPI == 2) ? 64 : 128;
    constexpr int TBN = (EPI == 2) ? 256 : 128;
    constexpr int TWM = (EPI == 2) ? 1 : 2;     // warps along M
    constexpr int AF  = TBM * LDS_;             // A stage floats
    constexpr int BF  = TBN * LDS_;
    constexpr int STF = AF + BF;

    extern __shared__ float smf[];
    float* rowsum = smf + 3 * STF;              // 64 floats (EPI2)

    const int tid  = threadIdx.x;
    const int wid  = tid >> 5, lane = tid & 31;
    const int m0   = blockIdx.y * TBM, n0 = blockIdx.x * TBN, z = blockIdx.z;
    const int wm   = wid % TWM;
    const int wn   = wid / TWM;
    const int gq   = lane >> 2;                 // groupID
    const int gc   = lane & 3;                  // thread in group

    const float* A  = gA + (size_t)z * sA + (size_t)m0 * lda;
    const float* Bp = gB + (size_t)z * sB + (size_t)n0 * ldb;
    const uint32_t sbase = smem_u32(smf);

    float acc[4][4][4];
#pragma unroll
    for (int i = 0; i < 4; i++)
#pragma unroll
        for (int j = 0; j < 4; j++)
#pragma unroll
            for (int k = 0; k < 4; k++) acc[i][j][k] = 0.f;

    // ---- async stage loader: A rows TBM x 32k, B rows TBN x 32k
    auto load_stage = [&](int stage, int k0) {
        const uint32_t ab = sbase + (uint32_t)(stage * STF) * 4u;
        const uint32_t bb = ab + (uint32_t)AF * 4u;
#pragma unroll
        for (int r = 0; r < TBM * 8 / 256; r++) {
            int u = tid + r * 256;
            int m = u >> 3, seg = u & 7;
            cp16(ab + (uint32_t)(m * (LDS_ * 4) + seg * 16),
                 A + (size_t)m * lda + k0 + seg * 4);
        }
#pragma unroll
        for (int r = 0; r < TBN * 8 / 256; r++) {
            int u = tid + r * 256;
            int n = u >> 3, seg = u & 7;
            cp16(bb + (uint32_t)(n * (LDS_ * 4) + seg * 16),
                 Bp + (size_t)n * ldb + k0 + seg * 4);
        }
        cp_commit();
    };

    load_stage(0, 0);
    load_stage(1, BKC);

    for (int i = 0; i < NIT; i++) {
        if (i < NIT - 1) cp_wait<1>(); else cp_wait<0>();
        __syncthreads();
        if (i + 2 < NIT) load_stage((i + 2) % 3, (i + 2) * BKC);

        const uint32_t* As = (const uint32_t*)(smf + (i % 3) * STF);
        const uint32_t* Bs = As + AF;

#pragma unroll
        for (int kk = 0; kk < BKC; kk += 8) {
            uint32_t af[4][4], bf[4][2];
            const int c = kk + gc;
#pragma unroll
            for (int mt = 0; mt < 4; mt++) {
                const int m = wm * 64 + mt * 16 + gq;
                af[mt][0] = As[m * LDS_ + c];
                af[mt][1] = As[(m + 8) * LDS_ + c];
                af[mt][2] = As[m * LDS_ + c + 4];
                af[mt][3] = As[(m + 8) * LDS_ + c + 4];
            }
#pragma unroll
            for (int nt = 0; nt < 4; nt++) {
                const int n = wn * 32 + nt * 8 + gq;
                bf[nt][0] = Bs[n * LDS_ + c];
                bf[nt][1] = Bs[n * LDS_ + c + 4];
            }
#pragma unroll
            for (int mt = 0; mt < 4; mt++)
#pragma unroll
                for (int nt = 0; nt < 4; nt++)
                    mma8(acc[mt][nt], af[mt], bf[nt]);
        }
    }
    // no trailing sync needed: stores below go to global

    // ---- epilogue
    if (EPI == 2) {
        // bias add into acc
#pragma unroll
        for (int nt = 0; nt < 4; nt++) {
            const int col = n0 + wn * 32 + nt * 8 + gc * 2;
            const float b0 = bias[col], b1 = bias[col + 1];
#pragma unroll
            for (int mt = 0; mt < 4; mt++) {
                acc[mt][nt][0] += b0; acc[mt][nt][1] += b1;
                acc[mt][nt][2] += b0; acc[mt][nt][3] += b1;
            }
        }
        if (tid < 64) rowsum[tid] = 0.f;
        __syncthreads();
        // per-row sum of squares; quad-reduce then one atomic per row
#pragma unroll
        for (int mt = 0; mt < 4; mt++) {
            float p0 = 0.f, p1 = 0.f;
#pragma unroll
            for (int nt = 0; nt < 4; nt++) {
                p0 = fmaf(acc[mt][nt][0], acc[mt][nt][0], p0);
                p0 = fmaf(acc[mt][nt][1], acc[mt][nt][1], p0);
                p1 = fmaf(acc[mt][nt][2], acc[mt][nt][2], p1);
                p1 = fmaf(acc[mt][nt][3], acc[mt][nt][3], p1);
            }
            p0 += __shfl_xor_sync(0xffffffffu, p0, 1);
            p0 += __shfl_xor_sync(0xffffffffu, p0, 2);
            p1 += __shfl_xor_sync(0xffffffffu, p1, 1);
            p1 += __shfl_xor_sync(0xffffffffu, p1, 2);
            if (gc == 0) {
                atomicAdd(&rowsum[mt * 16 + gq], p0);
                atomicAdd(&rowsum[mt * 16 + gq + 8], p1);
            }
        }
        __syncthreads();
#pragma unroll
        for (int mt = 0; mt < 4; mt++) {
            const int rr = mt * 16 + gq;
            const float s0 = 1.f / (sqrtf(rowsum[rr]) + EPSF);
            const float s1 = 1.f / (sqrtf(rowsum[rr + 8]) + EPSF);
            const int r = m0 + rr;
#pragma unroll
            for (int nt = 0; nt < 4; nt++) {
                const int col = n0 + wn * 32 + nt * 8 + gc * 2;
                float2 v0 = make_float2(acc[mt][nt][0] * s0, acc[mt][nt][1] * s0);
                float2 v1 = make_float2(acc[mt][nt][2] * s1, acc[mt][nt][3] * s1);
                *(float2*)(gD + (size_t)z * sD + (size_t)r * ldd + col) = v0;
                *(float2*)(gD + (size_t)z * sD + (size_t)(r + 8) * ldd + col) = v1;
            }
        }
    } else {
#pragma unroll
        for (int mt = 0; mt < 4; mt++) {
            const int r = m0 + wm * 64 + mt * 16 + gq;
#pragma unroll
            for (int nt = 0; nt < 4; nt++) {
                const int col = n0 + wn * 32 + nt * 8 + gc * 2;
                float x0 = acc[mt][nt][0], x1 = acc[mt][nt][1];
                float x2 = acc[mt][nt][2], x3 = acc[mt][nt][3];
                if (EPI == 0) {
                    x0 = lrelu(x0); x1 = lrelu(x1);
                    x2 = lrelu(x2); x3 = lrelu(x3);
                }
                *(float2*)(gD + (size_t)z * sD + (size_t)r * ldd + col) =
                    make_float2(x0, x1);
                *(float2*)(gD + (size_t)z * sD + (size_t)(r + 8) * ldd + col) =
                    make_float2(x2, x3);
            }
        }
    }
}

// ---------------------------------------------------------------------------
// Elementwise / reduction kernels
// ---------------------------------------------------------------------------
__global__ __launch_bounds__(256) void prep_qm_kernel(
    const float* __restrict__ q, const float* __restrict__ m)
{
    size_t i = (size_t)blockIdx.x * 256 + threadIdx.x;
    float4 a = ((const float4*)q)[i];
    float4 b = ((const float4*)m)[i];
    float4 r;
    r.x = frna(a.x * b.x); r.y = frna(a.y * b.y);
    r.z = frna(a.z * b.z); r.w = frna(a.w * b.w);
    ((float4*)g_qm)[i] = r;
}

__global__ __launch_bounds__(256) void prep_w_kernel(const float* __restrict__ W)
{
    size_t i = (size_t)blockIdx.x * 256 + threadIdx.x;
    float4 a = ((const float4*)W)[i];
    float4 r;
    r.x = frna(a.x); r.y = frna(a.y); r.z = frna(a.z); r.w = frna(a.w);
    ((float4*)g_w)[i] = r;
}

// ctx -> rna copy (ctxR) + rna transpose (ctxT), 32x32 tiles
__global__ __launch_bounds__(256) void prep_ctx_kernel(const float* __restrict__ ctx)
{
    __shared__ float t[32][33];
    const int b = blockIdx.z;
    const int d0 = blockIdx.x << 5, s0 = blockIdx.y << 5;
    const int tx = threadIdx.x & 31, ty = threadIdx.x >> 5;
    const float* src = ctx + (size_t)b * LS * DD;
    float* dstR = g_ctxR + (size_t)b * LS * DD;
#pragma unroll
    for (int j = 0; j < 4; j++) {
        const float v = frna(src[(size_t)(s0 + ty + j * 8) * DD + d0 + tx]);
        t[ty + j * 8][tx] = v;
        dstR[(size_t)(s0 + ty + j * 8) * DD + d0 + tx] = v;
    }
    __syncthreads();
    float* dstT = g_ctxT + (size_t)b * DD * LS;
#pragma unroll
    for (int j = 0; j < 4; j++)
        dstT[(size_t)(d0 + ty + j * 8) * LS + s0 + tx] = t[tx][ty + j * 8];
}

// l2-normalize over q for fixed (b, s): columns of (b, q, s)
__global__ __launch_bounds__(256) void colnorm_kernel()
{
    const int b = blockIdx.x >> 2;
    const int s = ((blockIdx.x & 3) << 8) | threadIdx.x;
    float* base = g_attn + (size_t)b * LQ * LS + s;
    float ss = 0.f;
#pragma unroll 8
    for (int q = 0; q < LQ; q++) {
        float v = base[(size_t)q * LS];
        ss = fmaf(v, v, ss);
    }
    const float inv = 1.f / (sqrtf(ss) + EPSF);
#pragma unroll 8
    for (int q = 0; q < LQ; q++)
        base[(size_t)q * LS] *= inv;
}

// softmax over s (rows of (b,q,s)); one warp per row; rna on write
__global__ __launch_bounds__(256) void softmax_kernel(const int* __restrict__ smooth_ptr)
{
    float sm;
    {
        int iv = *smooth_ptr;
        if (iv >= -1000000 && iv <= 1000000) sm = (float)iv;
        else                                  sm = __int_as_float(iv);
    }
    const int w = threadIdx.x >> 5, lane = threadIdx.x & 31;
    const size_t row = (size_t)blockIdx.x * 8 + w;
    float* p = g_attn + row * LS;

    float v[32];
    float mx = -3.4e38f;
#pragma unroll
    for (int i = 0; i < 32; i++) {
        v[i] = p[i * 32 + lane];
        mx = fmaxf(mx, v[i]);
    }
#pragma unroll
    for (int o = 16; o > 0; o >>= 1)
        mx = fmaxf(mx, __shfl_xor_sync(0xffffffffu, mx, o));
    float s = 0.f;
#pragma unroll
    for (int i = 0; i < 32; i++) {
        v[i] = __expf((v[i] - mx) * sm);
        s += v[i];
    }
#pragma unroll
    for (int o = 16; o > 0; o >>= 1)
        s += __shfl_xor_sync(0xffffffffu, s, o);
    const float inv = 1.f / s;
#pragma unroll
    for (int i = 0; i < 32; i++)
        p[i * 32 + lane] = frna(v[i] * inv);
}

// wc: l2norm over D, diff = query - wc_norm, store rna(diff^2) in place
__global__ __launch_bounds__(256) void diff2_kernel(const float* __restrict__ qry)
{
    __shared__ float red[8];
    const size_t row = blockIdx.x;
    float* wc = g_wc + row * DD;
    const float* qp = qry + row * DD;
    const int tid = threadIdx.x, w = tid >> 5, lane = tid & 31;

    float4 v = ((const float4*)wc)[tid];
    float ss = v.x * v.x + v.y * v.y + v.z * v.z + v.w * v.w;
#pragma unroll
    for (int o = 16; o > 0; o >>= 1)
        ss += __shfl_xor_sync(0xffffffffu, ss, o);
    if (lane == 0) red[w] = ss;
    __syncthreads();
    float tot = 0.f;
#pragma unroll
    for (int i = 0; i < 8; i++) tot += red[i];
    const float inv = 1.f / (sqrtf(tot) + EPSF);

    float4 q4 = ((const float4*)qp)[tid];
    float4 d;
    d.x = q4.x - v.x * inv; d.y = q4.y - v.y * inv;
    d.z = q4.z - v.z * inv; d.w = q4.w - v.w * inv;
    float4 r;
    r.x = frna(d.x * d.x); r.y = frna(d.y * d.y);
    r.z = frna(d.z * d.z); r.w = frna(d.w * d.w);
    ((float4*)wc)[tid] = r;
}

// ---------------------------------------------------------------------------
extern "C" void kernel_launch(void* const* d_in, const int* in_sizes, int n_in,
                              void* d_out, int out_size)
{
    const float* qry  = (const float*)d_in[0];   // (B, Lq, D)
    const float* ctx  = (const float*)d_in[1];   // (B, Ls, D)
    const float* mat  = (const float*)d_in[2];   // (B, Lq, D)
    const float* W    = (const float*)d_in[3];   // (S, D)
    const float* bias = (const float*)d_in[4];   // (S,)
    const int*   smp  = (const int*)d_in[5];     // smooth
    float* outp = (float*)d_out;

    float *pqm, *pctxR, *pctxT, *pattn, *pwc, *pw;
    cudaGetSymbolAddress((void**)&pqm,   g_qm);
    cudaGetSymbolAddress((void**)&pctxR, g_ctxR);
    cudaGetSymbolAddress((void**)&pctxT, g_ctxT);
    cudaGetSymbolAddress((void**)&pattn, g_attn);
    cudaGetSymbolAddress((void**)&pwc,   g_wc);
    cudaGetSymbolAddress((void**)&pw,    g_w);

    constexpr int SM01 = 3 * (128 * LDS_ + 128 * LDS_) * 4;           // 110592
    constexpr int SM2  = 3 * (64 * LDS_ + 256 * LDS_) * 4 + 256;      // 138496
    cudaFuncSetAttribute(mma_gemm<0>, cudaFuncAttributeMaxDynamicSharedMemorySize, SM01);
    cudaFuncSetAttribute(mma_gemm<1>, cudaFuncAttributeMaxDynamicSharedMemorySize, SM01);
    cudaFuncSetAttribute(mma_gemm<2>, cudaFuncAttributeMaxDynamicSharedMemorySize, SM2);

    // 1. qm = rna(query * matrix); ctxR/ctxT; w = rna(W)
    prep_qm_kernel<<<(B_ * LQ * DD) / 4 / 256, 256>>>(qry, mat);
    prep_ctx_kernel<<<dim3(DD / 32, LS / 32, B_), 256>>>(ctx);
    prep_w_kernel<<<(SS * DD) / 4 / 256, 256>>>(W);

    // 2. attn[b,q,s] = lrelu( qm[b,q,:] . ctxR[b,s,:] )
    mma_gemm<0><<<dim3(LS / 128, LQ / 128, B_), 256, SM01>>>(
        pqm, pctxR, pattn, nullptr,
        DD, DD, LS, (size_t)LQ * DD, (size_t)LS * DD, (size_t)LQ * LS);

    // 3. l2 normalize over q; 4. softmax over s (rna on write)
    colnorm_kernel<<<B_ * (LS / 256), 256>>>();
    softmax_kernel<<<B_ * LQ / 8, 256>>>(smp);

    // 5. wc[b,q,d] = attn[b,q,:] . ctxT[b,d,:]
    mma_gemm<1><<<dim3(DD / 128, LQ / 128, B_), 256, SM01>>>(
        pattn, pctxT, pwc, nullptr,
        LS, LS, DD, (size_t)LQ * LS, (size_t)DD * LS, (size_t)LQ * DD);

    // 6. l2norm wc + squared diff (rna), in place
    diff2_kernel<<<B_ * LQ, 256>>>(qry);

    // 7. sim = diff2 @ W^T + b, fused l2norm over S
    mma_gemm<2><<<dim3(SS / 256, LQ / 64, B_), 256, SM2>>>(
        pwc, pw, outp, bias,
        DD, DD, SS, (size_t)LQ * DD, 0, (size_t)LQ * SS);
}

// round 4
// speedup vs baseline: 4.2697x; 1.7493x over previous
#include <cuda_runtime.h>
#include <cuda_fp16.h>
#include <cstdint>
#include <math.h>

#define B_  32
#define LQ  512
#define LS  1024
#define DD  1024
#define SS  256
#define EPSF 1e-8f

// Scratch (allocation forbidden): device globals.
__device__ __half g_qmh [B_ * LQ * DD];   // fp16(query*matrix)   32MB
__device__ __half g_ctxh[B_ * LS * DD];   // fp16(ctx)            64MB
__device__ __half g_ctxt[B_ * DD * LS];   // fp16(ctx^T)          64MB
__device__ __half g_attn[B_ * LQ * LS];   // attn (b,q,s) fp16    32MB
__device__ __half g_wch [B_ * LQ * DD];   // wc -> diff^2 fp16    32MB
__device__ __half g_wh  [SS * DD];        // fp16(W)              0.5MB
__device__ float  g_cn  [B_ * LS];        // column sumsq -> inv  128KB

// ---------------------------------------------------------------------------
__device__ __forceinline__ uint32_t smem_u32(const void* p) {
    uint32_t a;
    asm("{ .reg .u64 t; cvta.to.shared.u64 t, %1; cvt.u32.u64 %0, t; }"
        : "=r"(a) : "l"(p));
    return a;
}
__device__ __forceinline__ float lrelu(float x) { return x > 0.f ? x : 0.1f * x; }

__device__ __forceinline__ void cp16(uint32_t s, const void* g) {
    asm volatile("cp.async.cg.shared.global [%0], [%1], 16;" :: "r"(s), "l"(g));
}
__device__ __forceinline__ void cp_commit() {
    asm volatile("cp.async.commit_group;" ::: "memory");
}
template <int N> __device__ __forceinline__ void cp_wait() {
    asm volatile("cp.async.wait_group %0;" :: "n"(N) : "memory");
}

// m16n8k16 fp16 inputs, fp32 accumulate (baseline PTX, sm_80+)
__device__ __forceinline__ void mma16(float* c, const uint32_t* a, const uint32_t* b) {
    asm volatile(
        "mma.sync.aligned.m16n8k16.row.col.f32.f16.f16.f32 "
        "{%0,%1,%2,%3}, {%4,%5,%6,%7}, {%8,%9}, {%0,%1,%2,%3};"
        : "+f"(c[0]), "+f"(c[1]), "+f"(c[2]), "+f"(c[3])
        : "r"(a[0]), "r"(a[1]), "r"(a[2]), "r"(a[3]), "r"(b[0]), "r"(b[1]));
}

// ---------------------------------------------------------------------------
// fp16 warp-MMA GEMM: D[m,n] = sum_k A[m,k] * B[n,k]  (K=1024, K-major fp16)
//   EPI 0: leaky_relu, store fp16, fused column-sumsq atomics  (attn)
//   EPI 1: raw fp16 store                                      (wcontext)
//   EPI 2: +bias, fused l2norm over N=256, fp32 store          (out)
// ---------------------------------------------------------------------------
#define KTOT 1024
#define BKC  64                 // fp16 k per chunk
#define NIT  (KTOT / BKC)       // 16
#define LDB32 36                // padded row length in b32 units (32 + 4)

template <int EPI>
__global__ __launch_bounds__(256, 1) void hgemm(
    const __half* __restrict__ gA, const __half* __restrict__ gB,
    void* __restrict__ gDv, const float* __restrict__ bias,
    float* __restrict__ cnorm,
    int lda, int ldb, int ldd, size_t sA, size_t sB, size_t sD)
{
    constexpr int TBM = (EPI == 2) ? 64 : 128;
    constexpr int TBN = (EPI == 2) ? 256 : 128;
    constexpr int TWM = (EPI == 2) ? 1 : 2;     // warps along M
    constexpr int AF  = TBM * LDB32;            // b32 units per A stage
    constexpr int BF  = TBN * LDB32;
    constexpr int STF = AF + BF;

    extern __shared__ uint32_t smu[];
    float* redbuf = (float*)(smu + 3 * STF);    // 128 floats (EPI0) / 64 (EPI2)

    const int tid  = threadIdx.x;
    const int wid  = tid >> 5, lane = tid & 31;
    const int m0   = blockIdx.y * TBM, n0 = blockIdx.x * TBN, z = blockIdx.z;
    const int wm   = wid % TWM;
    const int wn   = wid / TWM;
    const int gq   = lane >> 2;                 // row in group
    const int gc   = lane & 3;                  // thread in group

    const __half* A  = gA + (size_t)z * sA + (size_t)m0 * lda;
    const __half* Bp = gB + (size_t)z * sB + (size_t)n0 * ldb;
    const uint32_t sbase = smem_u32(smu);

    if (EPI == 0 && tid < TBN / 2) { redbuf[tid] = 0.f; redbuf[tid + TBN / 2] = 0.f; }

    float acc[4][4][4];
#pragma unroll
    for (int i = 0; i < 4; i++)
#pragma unroll
        for (int j = 0; j < 4; j++)
#pragma unroll
            for (int k = 0; k < 4; k++) acc[i][j][k] = 0.f;

    // stage loader: rows are BKC fp16 = 128B = 8 x 16B segments
    auto load_stage = [&](int stage, int k0) {
        const uint32_t ab = sbase + (uint32_t)(stage * STF) * 4u;
        const uint32_t bb = ab + (uint32_t)AF * 4u;
#pragma unroll
        for (int r = 0; r < TBM * 8 / 256; r++) {
            int u = tid + r * 256;
            int m = u >> 3, seg = u & 7;
            cp16(ab + (uint32_t)(m * (LDB32 * 4) + seg * 16),
                 A + (size_t)m * lda + k0 + seg * 8);
        }
#pragma unroll
        for (int r = 0; r < TBN * 8 / 256; r++) {
            int u = tid + r * 256;
            int n = u >> 3, seg = u & 7;
            cp16(bb + (uint32_t)(n * (LDB32 * 4) + seg * 16),
                 Bp + (size_t)n * ldb + k0 + seg * 8);
        }
        cp_commit();
    };

    load_stage(0, 0);
    load_stage(1, BKC);

    for (int i = 0; i < NIT; i++) {
        if (i < NIT - 1) cp_wait<1>(); else cp_wait<0>();
        __syncthreads();
        if (i + 2 < NIT) load_stage((i + 2) % 3, (i + 2) * BKC);

        const uint32_t* As = smu + (i % 3) * STF;
        const uint32_t* Bs = As + AF;

#pragma unroll
        for (int ks = 0; ks < 4; ks++) {        // 4 x k16 per chunk
            uint32_t af[4][4], bf[4][2];
            const int c = ks * 8 + gc;
#pragma unroll
            for (int mt = 0; mt < 4; mt++) {
                const int m = wm * 64 + mt * 16 + gq;
                af[mt][0] = As[m * LDB32 + c];
                af[mt][1] = As[(m + 8) * LDB32 + c];
                af[mt][2] = As[m * LDB32 + c + 4];
                af[mt][3] = As[(m + 8) * LDB32 + c + 4];
            }
#pragma unroll
            for (int nt = 0; nt < 4; nt++) {
                const int n = wn * 32 + nt * 8 + gq;
                bf[nt][0] = Bs[n * LDB32 + c];
                bf[nt][1] = Bs[n * LDB32 + c + 4];
            }
#pragma unroll
            for (int mt = 0; mt < 4; mt++)
#pragma unroll
                for (int nt = 0; nt < 4; nt++)
                    mma16(acc[mt][nt], af[mt], bf[nt]);
        }
    }

    // ---- epilogues
    if (EPI == 2) {
        float* gD = (float*)gDv;
#pragma unroll
        for (int nt = 0; nt < 4; nt++) {
            const int col = n0 + wn * 32 + nt * 8 + gc * 2;
            const float b0 = bias[col], b1 = bias[col + 1];
#pragma unroll
            for (int mt = 0; mt < 4; mt++) {
                acc[mt][nt][0] += b0; acc[mt][nt][1] += b1;
                acc[mt][nt][2] += b0; acc[mt][nt][3] += b1;
            }
        }
        if (tid < 64) redbuf[tid] = 0.f;
        __syncthreads();
#pragma unroll
        for (int mt = 0; mt < 4; mt++) {
            float p0 = 0.f, p1 = 0.f;
#pragma unroll
            for (int nt = 0; nt < 4; nt++) {
                p0 = fmaf(acc[mt][nt][0], acc[mt][nt][0], p0);
                p0 = fmaf(acc[mt][nt][1], acc[mt][nt][1], p0);
                p1 = fmaf(acc[mt][nt][2], acc[mt][nt][2], p1);
                p1 = fmaf(acc[mt][nt][3], acc[mt][nt][3], p1);
            }
            p0 += __shfl_xor_sync(0xffffffffu, p0, 1);
            p0 += __shfl_xor_sync(0xffffffffu, p0, 2);
            p1 += __shfl_xor_sync(0xffffffffu, p1, 1);
            p1 += __shfl_xor_sync(0xffffffffu, p1, 2);
            if (gc == 0) {
                atomicAdd(&redbuf[mt * 16 + gq], p0);
                atomicAdd(&redbuf[mt * 16 + gq + 8], p1);
            }
        }
        __syncthreads();
#pragma unroll
        for (int mt = 0; mt < 4; mt++) {
            const int rr = mt * 16 + gq;
            const float s0 = 1.f / (sqrtf(redbuf[rr]) + EPSF);
            const float s1 = 1.f / (sqrtf(redbuf[rr + 8]) + EPSF);
            const int r = m0 + rr;
#pragma unroll
            for (int nt = 0; nt < 4; nt++) {
                const int col = n0 + wn * 32 + nt * 8 + gc * 2;
                *(float2*)(gD + (size_t)z * sD + (size_t)r * ldd + col) =
                    make_float2(acc[mt][nt][0] * s0, acc[mt][nt][1] * s0);
                *(float2*)(gD + (size_t)z * sD + (size_t)(r + 8) * ldd + col) =
                    make_float2(acc[mt][nt][2] * s1, acc[mt][nt][3] * s1);
            }
        }
    } else {
        __half* gD = (__half*)gDv;
#pragma unroll
        for (int mt = 0; mt < 4; mt++) {
            const int r = m0 + wm * 64 + mt * 16 + gq;
#pragma unroll
            for (int nt = 0; nt < 4; nt++) {
                const int col = n0 + wn * 32 + nt * 8 + gc * 2;
                float x0 = acc[mt][nt][0], x1 = acc[mt][nt][1];
                float x2 = acc[mt][nt][2], x3 = acc[mt][nt][3];
                if (EPI == 0) {
                    x0 = lrelu(x0); x1 = lrelu(x1);
                    x2 = lrelu(x2); x3 = lrelu(x3);
                    // fused column sum-of-squares (l2norm over q)
                    float p0 = fmaf(x0, x0, x2 * x2);
                    float p1 = fmaf(x1, x1, x3 * x3);
                    acc[mt][nt][0] = x0; acc[mt][nt][1] = x1;
                    acc[mt][nt][2] = x2; acc[mt][nt][3] = x3;
                    p0 += __shfl_xor_sync(0xffffffffu, p0, 4);
                    p0 += __shfl_xor_sync(0xffffffffu, p0, 8);
                    p0 += __shfl_xor_sync(0xffffffffu, p0, 16);
                    p1 += __shfl_xor_sync(0xffffffffu, p1, 4);
                    p1 += __shfl_xor_sync(0xffffffffu, p1, 8);
                    p1 += __shfl_xor_sync(0xffffffffu, p1, 16);
                    if (gq == 0) {
                        const int lc = wn * 32 + nt * 8 + gc * 2;
                        atomicAdd(&redbuf[lc], p0);
                        atomicAdd(&redbuf[lc + 1], p1);
                    }
                }
                *(__half2*)(gD + (size_t)z * sD + (size_t)r * ldd + col) =
                    __floats2half2_rn(x0, x1);
                *(__half2*)(gD + (size_t)z * sD + (size_t)(r + 8) * ldd + col) =
                    __floats2half2_rn(x2, x3);
            }
        }
        if (EPI == 0) {
            __syncthreads();
            if (tid < TBN)
                atomicAdd(&cnorm[(size_t)z * LS + n0 + tid], redbuf[tid]);
        }
    }
}

// ---------------------------------------------------------------------------
// Elementwise / prep kernels
// ---------------------------------------------------------------------------
__global__ __launch_bounds__(256) void zero_cn_kernel()
{
    g_cn[blockIdx.x * 256 + threadIdx.x] = 0.f;
}
__global__ __launch_bounds__(256) void inv_cn_kernel()
{
    const int i = blockIdx.x * 256 + threadIdx.x;
    g_cn[i] = 1.f / (sqrtf(g_cn[i]) + EPSF);
}

__global__ __launch_bounds__(256) void prep_qm_kernel(
    const float* __restrict__ q, const float* __restrict__ m)
{
    size_t i = (size_t)blockIdx.x * 256 + threadIdx.x;
    float4 a = ((const float4*)q)[i];
    float4 b = ((const float4*)m)[i];
    ((__half2*)g_qmh)[2 * i]     = __floats2half2_rn(a.x * b.x, a.y * b.y);
    ((__half2*)g_qmh)[2 * i + 1] = __floats2half2_rn(a.z * b.z, a.w * b.w);
}

__global__ __launch_bounds__(256) void prep_w_kernel(const float* __restrict__ W)
{
    size_t i = (size_t)blockIdx.x * 256 + threadIdx.x;
    float4 a = ((const float4*)W)[i];
    ((__half2*)g_wh)[2 * i]     = __floats2half2_rn(a.x, a.y);
    ((__half2*)g_wh)[2 * i + 1] = __floats2half2_rn(a.z, a.w);
}

// ctx -> fp16 copy + fp16 transpose, 32x32 tiles
__global__ __launch_bounds__(256) void prep_ctx_kernel(const float* __restrict__ ctx)
{
    __shared__ float t[32][33];
    const int b = blockIdx.z;
    const int d0 = blockIdx.x << 5, s0 = blockIdx.y << 5;
    const int tx = threadIdx.x & 31, ty = threadIdx.x >> 5;
    const float* src = ctx + (size_t)b * LS * DD;
    __half* dstR = g_ctxh + (size_t)b * LS * DD;
#pragma unroll
    for (int j = 0; j < 4; j++) {
        const float v = src[(size_t)(s0 + ty + j * 8) * DD + d0 + tx];
        t[ty + j * 8][tx] = v;
        dstR[(size_t)(s0 + ty + j * 8) * DD + d0 + tx] = __float2half_rn(v);
    }
    __syncthreads();
    __half* dstT = g_ctxt + (size_t)b * DD * LS;
#pragma unroll
    for (int j = 0; j < 4; j++)
        dstT[(size_t)(d0 + ty + j * 8) * LS + s0 + tx] =
            __float2half_rn(t[tx][ty + j * 8]);
}

// softmax over s for each (b,q) row; divide by column norm first; in place fp16
__global__ __launch_bounds__(256) void softmax_kernel(const int* __restrict__ smooth_ptr)
{
    float sm;
    {
        int iv = *smooth_ptr;
        if (iv >= -1000000 && iv <= 1000000) sm = (float)iv;
        else                                  sm = __int_as_float(iv);
    }
    const int w = threadIdx.x >> 5, lane = threadIdx.x & 31;
    const size_t row = (size_t)blockIdx.x * 8 + w;       // b*LQ + q
    const int b = (int)(row >> 9);
    __half* p = g_attn + row * LS;
    const float* cinv = g_cn + (size_t)b * LS;

    float v[32];
    float mx = -3.4e38f;
#pragma unroll
    for (int i = 0; i < 32; i++) {
        const int s = i * 32 + lane;
        v[i] = __half2float(p[s]) * cinv[s] * sm;
        mx = fmaxf(mx, v[i]);
    }
#pragma unroll
    for (int o = 16; o > 0; o >>= 1)
        mx = fmaxf(mx, __shfl_xor_sync(0xffffffffu, mx, o));
    float s = 0.f;
#pragma unroll
    for (int i = 0; i < 32; i++) {
        v[i] = __expf(v[i] - mx);
        s += v[i];
    }
#pragma unroll
    for (int o = 16; o > 0; o >>= 1)
        s += __shfl_xor_sync(0xffffffffu, s, o);
    const float inv = 1.f / s;
#pragma unroll
    for (int i = 0; i < 32; i++)
        p[i * 32 + lane] = __float2half_rn(v[i] * inv);
}

// wc (fp16): l2norm over D, diff = query - wc_norm, store fp16(diff^2) in place
__global__ __launch_bounds__(256) void diff2_kernel(const float* __restrict__ qry)
{
    __shared__ float red[8];
    const size_t row = blockIdx.x;
    __half2* wc = (__half2*)(g_wch + row * DD);
    const float* qp = qry + row * DD;
    const int tid = threadIdx.x, w = tid >> 5, lane = tid & 31;

    float2 v0 = __half22float2(wc[tid * 2]);
    float2 v1 = __half22float2(wc[tid * 2 + 1]);
    float ss = v0.x * v0.x + v0.y * v0.y + v1.x * v1.x + v1.y * v1.y;
#pragma unroll
    for (int o = 16; o > 0; o >>= 1)
        ss += __shfl_xor_sync(0xffffffffu, ss, o);
    if (lane == 0) red[w] = ss;
    __syncthreads();
    float tot = 0.f;
#pragma unroll
    for (int i = 0; i < 8; i++) tot += red[i];
    const float inv = 1.f / (sqrtf(tot) + EPSF);

    float4 q4 = ((const float4*)qp)[tid];
    const float d0 = q4.x - v0.x * inv, d1 = q4.y - v0.y * inv;
    const float d2 = q4.z - v1.x * inv, d3 = q4.w - v1.y * inv;
    wc[tid * 2]     = __floats2half2_rn(d0 * d0, d1 * d1);
    wc[tid * 2 + 1] = __floats2half2_rn(d2 * d2, d3 * d3);
}

// ---------------------------------------------------------------------------
extern "C" void kernel_launch(void* const* d_in, const int* in_sizes, int n_in,
                              void* d_out, int out_size)
{
    const float* qry  = (const float*)d_in[0];   // (B, Lq, D)
    const float* ctx  = (const float*)d_in[1];   // (B, Ls, D)
    const float* mat  = (const float*)d_in[2];   // (B, Lq, D)
    const float* W    = (const float*)d_in[3];   // (S, D)
    const float* bias = (const float*)d_in[4];   // (S,)
    const int*   smp  = (const int*)d_in[5];     // smooth
    float* outp = (float*)d_out;

    __half *pqm, *pctxh, *pctxt, *pattn, *pwch, *pwh;
    float* pcn;
    cudaGetSymbolAddress((void**)&pqm,   g_qmh);
    cudaGetSymbolAddress((void**)&pctxh, g_ctxh);
    cudaGetSymbolAddress((void**)&pctxt, g_ctxt);
    cudaGetSymbolAddress((void**)&pattn, g_attn);
    cudaGetSymbolAddress((void**)&pwch,  g_wch);
    cudaGetSymbolAddress((void**)&pwh,   g_wh);
    cudaGetSymbolAddress((void**)&pcn,   g_cn);

    constexpr int SM01 = 3 * (128 + 128) * LDB32 * 4 + 512;   // 111104
    constexpr int SM2  = 3 * (64 + 256) * LDB32 * 4 + 256;    // 138496
    cudaFuncSetAttribute(hgemm<0>, cudaFuncAttributeMaxDynamicSharedMemorySize, SM01);
    cudaFuncSetAttribute(hgemm<1>, cudaFuncAttributeMaxDynamicSharedMemorySize, SM01);
    cudaFuncSetAttribute(hgemm<2>, cudaFuncAttributeMaxDynamicSharedMemorySize, SM2);

    // prep: fp16 operands
    prep_qm_kernel<<<(B_ * LQ * DD) / 4 / 256, 256>>>(qry, mat);
    prep_ctx_kernel<<<dim3(DD / 32, LS / 32, B_), 256>>>(ctx);
    prep_w_kernel<<<(SS * DD) / 4 / 256, 256>>>(W);
    zero_cn_kernel<<<(B_ * LS) / 256, 256>>>();

    // attn = lrelu(qm . ctx^T), fused column sumsq
    hgemm<0><<<dim3(LS / 128, LQ / 128, B_), 256, SM01>>>(
        pqm, pctxh, pattn, nullptr, pcn,
        DD, DD, LS, (size_t)LQ * DD, (size_t)LS * DD, (size_t)LQ * LS);

    // 1/(sqrt(colnorm)+eps), then softmax over s (fused colnorm divide)
    inv_cn_kernel<<<(B_ * LS) / 256, 256>>>();
    softmax_kernel<<<B_ * LQ / 8, 256>>>(smp);

    // wc = attn . ctxT^T
    hgemm<1><<<dim3(DD / 128, LQ / 128, B_), 256, SM01>>>(
        pattn, pctxt, pwch, nullptr, nullptr,
        LS, LS, DD, (size_t)LQ * LS, (size_t)DD * LS, (size_t)LQ * DD);

    // l2norm(wc) + squared diff, in place fp16
    diff2_kernel<<<B_ * LQ, 256>>>(qry);

    // out = diff2 . W^T + b, fused l2norm over S
    hgemm<2><<<dim3(SS / 256, LQ / 64, B_), 256, SM2>>>(
        pwch, pwh, outp, bias, nullptr,
        DD, DD, SS, (size_t)LQ * DD, 0, (size_t)LQ * SS);
}

// round 5
// speedup vs baseline: 5.1648x; 1.2097x over previous
#include <cuda_runtime.h>
#include <cuda_fp16.h>
#include <cstdint>
#include <math.h>

#define B_  32
#define LQ  512
#define LS  1024
#define DD  1024
#define SS  256
#define EPSF 1e-8f

// Scratch (allocation forbidden): device globals.
__device__ __half g_qmh [B_ * LQ * DD];   // fp16(query*matrix)   32MB
__device__ __half g_ctxh[B_ * LS * DD];   // fp16(ctx)            64MB
__device__ __half g_ctxt[B_ * DD * LS];   // fp16(ctx^T)          64MB
__device__ __half g_attn[B_ * LQ * LS];   // attn (b,q,s) fp16    32MB
__device__ __half g_wch [B_ * LQ * DD];   // wc -> diff^2 fp16    32MB
__device__ __half g_wh  [SS * DD];        // fp16(W)              0.5MB
__device__ float  g_cn  [B_ * LS];        // column sumsq -> inv  128KB

// ---------------------------------------------------------------------------
__device__ __forceinline__ uint32_t smem_u32(const void* p) {
    uint32_t a;
    asm("{ .reg .u64 t; cvta.to.shared.u64 t, %1; cvt.u32.u64 %0, t; }"
        : "=r"(a) : "l"(p));
    return a;
}
__device__ __forceinline__ float lrelu(float x) { return x > 0.f ? x : 0.1f * x; }

__device__ __forceinline__ void cp16(uint32_t s, const void* g) {
    asm volatile("cp.async.cg.shared.global [%0], [%1], 16;" :: "r"(s), "l"(g));
}
__device__ __forceinline__ void cp_commit() {
    asm volatile("cp.async.commit_group;" ::: "memory");
}
template <int N> __device__ __forceinline__ void cp_wait() {
    asm volatile("cp.async.wait_group %0;" :: "n"(N) : "memory");
}

// m16n8k16 fp16 inputs, fp32 accumulate
__device__ __forceinline__ void mma16(float* c, const uint32_t* a, const uint32_t* b) {
    asm volatile(
        "mma.sync.aligned.m16n8k16.row.col.f32.f16.f16.f32 "
        "{%0,%1,%2,%3}, {%4,%5,%6,%7}, {%8,%9}, {%0,%1,%2,%3};"
        : "+f"(c[0]), "+f"(c[1]), "+f"(c[2]), "+f"(c[3])
        : "r"(a[0]), "r"(a[1]), "r"(a[2]), "r"(a[3]), "r"(b[0]), "r"(b[1]));
}
__device__ __forceinline__ void ldsm4(uint32_t* r, uint32_t addr) {
    asm volatile("ldmatrix.sync.aligned.m8n8.x4.shared.b16 {%0,%1,%2,%3}, [%4];"
        : "=r"(r[0]), "=r"(r[1]), "=r"(r[2]), "=r"(r[3]) : "r"(addr));
}

// ---------------------------------------------------------------------------
// fp16 warp-MMA GEMM: D[m,n] = sum_k A[m,k] * B[n,k]  (K=1024, K-major fp16)
//   EPI 0: leaky_relu, store fp16, fused column-sumsq atomics  (attn)
//   EPI 1: raw fp16 store                                      (wcontext)
//   EPI 2: +bias, fused l2norm over N=256, fp32 store          (out)
// ---------------------------------------------------------------------------
#define KTOT 1024
#define BKC  64                 // fp16 k per chunk
#define NIT  (KTOT / BKC)       // 16
#define LDB32 36                // padded row length in b32 units
#define ROWB  (LDB32 * 4)       // 144 bytes per row

template <int EPI>
__global__ __launch_bounds__(256, (EPI == 2) ? 1 : 2) void hgemm(
    const __half* __restrict__ gA, const __half* __restrict__ gB,
    void* __restrict__ gDv, const float* __restrict__ bias,
    float* __restrict__ cnorm,
    int lda, int ldb, int ldd, size_t sA, size_t sB, size_t sD)
{
    constexpr int TBM = (EPI == 2) ? 64 : 128;
    constexpr int TBN = (EPI == 2) ? 256 : 128;
    constexpr int TWM = (EPI == 2) ? 1 : 2;     // warps along M
    constexpr int AF  = TBM * LDB32;            // b32 units per A stage
    constexpr int BF  = TBN * LDB32;
    constexpr int STF = AF + BF;

    extern __shared__ uint32_t smu[];
    float* redbuf = (float*)(smu + 3 * STF);

    const int tid  = threadIdx.x;
    const int wid  = tid >> 5, lane = tid & 31;
    const int m0   = blockIdx.y * TBM, n0 = blockIdx.x * TBN, z = blockIdx.z;
    const int wm   = wid % TWM;
    const int wn   = wid / TWM;
    const int gq   = lane >> 2;                 // row in group
    const int gc   = lane & 3;                  // thread in group

    const __half* A  = gA + (size_t)z * sA + (size_t)m0 * lda;
    const __half* Bp = gB + (size_t)z * sB + (size_t)n0 * ldb;
    const uint32_t sbase = smem_u32(smu);

    // ldmatrix per-lane byte offsets (within a stage)
    const int lr = lane & 7;
    const uint32_t aoff = (uint32_t)(wm * 64 + lr + ((lane >> 3) & 1) * 8) * ROWB
                        + (uint32_t)(lane >> 4) * 16;
    const uint32_t boff = (uint32_t)(wn * 32 + lr + (lane >> 4) * 8) * ROWB
                        + (uint32_t)((lane >> 3) & 1) * 16
                        + (uint32_t)AF * 4u;

    if (EPI == 0 && tid < TBN / 2) { redbuf[tid] = 0.f; redbuf[tid + TBN / 2] = 0.f; }

    float acc[4][4][4];
#pragma unroll
    for (int i = 0; i < 4; i++)
#pragma unroll
        for (int j = 0; j < 4; j++)
#pragma unroll
            for (int k = 0; k < 4; k++) acc[i][j][k] = 0.f;

    auto load_stage = [&](int stage, int k0) {
        const uint32_t ab = sbase + (uint32_t)(stage * STF) * 4u;
        const uint32_t bb = ab + (uint32_t)AF * 4u;
#pragma unroll
        for (int r = 0; r < TBM * 8 / 256; r++) {
            int u = tid + r * 256;
            int m = u >> 3, seg = u & 7;
            cp16(ab + (uint32_t)(m * ROWB + seg * 16),
                 A + (size_t)m * lda + k0 + seg * 8);
        }
#pragma unroll
        for (int r = 0; r < TBN * 8 / 256; r++) {
            int u = tid + r * 256;
            int n = u >> 3, seg = u & 7;
            cp16(bb + (uint32_t)(n * ROWB + seg * 16),
                 Bp + (size_t)n * ldb + k0 + seg * 8);
        }
        cp_commit();
    };

    load_stage(0, 0);
    load_stage(1, BKC);

    for (int i = 0; i < NIT; i++) {
        if (i < NIT - 1) cp_wait<1>(); else cp_wait<0>();
        __syncthreads();
        if (i + 2 < NIT) load_stage((i + 2) % 3, (i + 2) * BKC);

        const uint32_t stA = sbase + (uint32_t)((i % 3) * STF) * 4u;

#pragma unroll
        for (int ks = 0; ks < 4; ks++) {        // 4 x k16 per chunk
            uint32_t af[4][4], bf[4][2];
            const uint32_t ka = stA + ks * 32;
#pragma unroll
            for (int mt = 0; mt < 4; mt++)
                ldsm4(af[mt], ka + aoff + (uint32_t)(mt * 16 * ROWB));
#pragma unroll
            for (int np = 0; np < 2; np++) {
                uint32_t t[4];
                ldsm4(t, ka + boff + (uint32_t)(np * 16 * ROWB));
                bf[np * 2][0] = t[0]; bf[np * 2][1] = t[1];
                bf[np * 2 + 1][0] = t[2]; bf[np * 2 + 1][1] = t[3];
            }
#pragma unroll
            for (int mt = 0; mt < 4; mt++)
#pragma unroll
                for (int nt = 0; nt < 4; nt++)
                    mma16(acc[mt][nt], af[mt], bf[nt]);
        }
    }

    // ---- epilogues
    if (EPI == 2) {
        float* gD = (float*)gDv;
#pragma unroll
        for (int nt = 0; nt < 4; nt++) {
            const int col = n0 + wn * 32 + nt * 8 + gc * 2;
            const float b0 = bias[col], b1 = bias[col + 1];
#pragma unroll
            for (int mt = 0; mt < 4; mt++) {
                acc[mt][nt][0] += b0; acc[mt][nt][1] += b1;
                acc[mt][nt][2] += b0; acc[mt][nt][3] += b1;
            }
        }
        if (tid < 64) redbuf[tid] = 0.f;
        __syncthreads();
#pragma unroll
        for (int mt = 0; mt < 4; mt++) {
            float p0 = 0.f, p1 = 0.f;
#pragma unroll
            for (int nt = 0; nt < 4; nt++) {
                p0 = fmaf(acc[mt][nt][0], acc[mt][nt][0], p0);
                p0 = fmaf(acc[mt][nt][1], acc[mt][nt][1], p0);
                p1 = fmaf(acc[mt][nt][2], acc[mt][nt][2], p1);
                p1 = fmaf(acc[mt][nt][3], acc[mt][nt][3], p1);
            }
            p0 += __shfl_xor_sync(0xffffffffu, p0, 1);
            p0 += __shfl_xor_sync(0xffffffffu, p0, 2);
            p1 += __shfl_xor_sync(0xffffffffu, p1, 1);
            p1 += __shfl_xor_sync(0xffffffffu, p1, 2);
            if (gc == 0) {
                atomicAdd(&redbuf[mt * 16 + gq], p0);
                atomicAdd(&redbuf[mt * 16 + gq + 8], p1);
            }
        }
        __syncthreads();
#pragma unroll
        for (int mt = 0; mt < 4; mt++) {
            const int rr = mt * 16 + gq;
            const float s0 = 1.f / (sqrtf(redbuf[rr]) + EPSF);
            const float s1 = 1.f / (sqrtf(redbuf[rr + 8]) + EPSF);
            const int r = m0 + rr;
#pragma unroll
            for (int nt = 0; nt < 4; nt++) {
                const int col = n0 + wn * 32 + nt * 8 + gc * 2;
                *(float2*)(gD + (size_t)z * sD + (size_t)r * ldd + col) =
                    make_float2(acc[mt][nt][0] * s0, acc[mt][nt][1] * s0);
                *(float2*)(gD + (size_t)z * sD + (size_t)(r + 8) * ldd + col) =
                    make_float2(acc[mt][nt][2] * s1, acc[mt][nt][3] * s1);
            }
        }
    } else {
        __half* gD = (__half*)gDv;
#pragma unroll
        for (int mt = 0; mt < 4; mt++) {
            const int r = m0 + wm * 64 + mt * 16 + gq;
#pragma unroll
            for (int nt = 0; nt < 4; nt++) {
                const int col = n0 + wn * 32 + nt * 8 + gc * 2;
                float x0 = acc[mt][nt][0], x1 = acc[mt][nt][1];
                float x2 = acc[mt][nt][2], x3 = acc[mt][nt][3];
                if (EPI == 0) {
                    x0 = lrelu(x0); x1 = lrelu(x1);
                    x2 = lrelu(x2); x3 = lrelu(x3);
                    float p0 = fmaf(x0, x0, x2 * x2);
                    float p1 = fmaf(x1, x1, x3 * x3);
                    p0 += __shfl_xor_sync(0xffffffffu, p0, 4);
                    p0 += __shfl_xor_sync(0xffffffffu, p0, 8);
                    p0 += __shfl_xor_sync(0xffffffffu, p0, 16);
                    p1 += __shfl_xor_sync(0xffffffffu, p1, 4);
                    p1 += __shfl_xor_sync(0xffffffffu, p1, 8);
                    p1 += __shfl_xor_sync(0xffffffffu, p1, 16);
                    if (gq == 0) {
                        const int lc = wn * 32 + nt * 8 + gc * 2;
                        atomicAdd(&redbuf[lc], p0);
                        atomicAdd(&redbuf[lc + 1], p1);
                    }
                }
                *(__half2*)(gD + (size_t)z * sD + (size_t)r * ldd + col) =
                    __floats2half2_rn(x0, x1);
                *(__half2*)(gD + (size_t)z * sD + (size_t)(r + 8) * ldd + col) =
                    __floats2half2_rn(x2, x3);
            }
        }
        if (EPI == 0) {
            __syncthreads();
            if (tid < TBN)
                atomicAdd(&cnorm[(size_t)z * LS + n0 + tid], redbuf[tid]);
        }
    }
}

// ---------------------------------------------------------------------------
// Elementwise / prep kernels
// ---------------------------------------------------------------------------
__global__ __launch_bounds__(256) void zero_cn_kernel()
{
    g_cn[blockIdx.x * 256 + threadIdx.x] = 0.f;
}
__global__ __launch_bounds__(256) void inv_cn_kernel()
{
    const int i = blockIdx.x * 256 + threadIdx.x;
    g_cn[i] = 1.f / (sqrtf(g_cn[i]) + EPSF);
}

__global__ __launch_bounds__(256) void prep_qm_kernel(
    const float* __restrict__ q, const float* __restrict__ m)
{
    size_t i = (size_t)blockIdx.x * 256 + threadIdx.x;
    float4 a = ((const float4*)q)[i];
    float4 b = ((const float4*)m)[i];
    ((__half2*)g_qmh)[2 * i]     = __floats2half2_rn(a.x * b.x, a.y * b.y);
    ((__half2*)g_qmh)[2 * i + 1] = __floats2half2_rn(a.z * b.z, a.w * b.w);
}

__global__ __launch_bounds__(256) void prep_w_kernel(const float* __restrict__ W)
{
    size_t i = (size_t)blockIdx.x * 256 + threadIdx.x;
    float4 a = ((const float4*)W)[i];
    ((__half2*)g_wh)[2 * i]     = __floats2half2_rn(a.x, a.y);
    ((__half2*)g_wh)[2 * i + 1] = __floats2half2_rn(a.z, a.w);
}

__global__ __launch_bounds__(256) void prep_ctx_kernel(const float* __restrict__ ctx)
{
    __shared__ float t[32][33];
    const int b = blockIdx.z;
    const int d0 = blockIdx.x << 5, s0 = blockIdx.y << 5;
    const int tx = threadIdx.x & 31, ty = threadIdx.x >> 5;
    const float* src = ctx + (size_t)b * LS * DD;
    __half* dstR = g_ctxh + (size_t)b * LS * DD;
#pragma unroll
    for (int j = 0; j < 4; j++) {
        const float v = src[(size_t)(s0 + ty + j * 8) * DD + d0 + tx];
        t[ty + j * 8][tx] = v;
        dstR[(size_t)(s0 + ty + j * 8) * DD + d0 + tx] = __float2half_rn(v);
    }
    __syncthreads();
    __half* dstT = g_ctxt + (size_t)b * DD * LS;
#pragma unroll
    for (int j = 0; j < 4; j++)
        dstT[(size_t)(d0 + ty + j * 8) * LS + s0 + tx] =
            __float2half_rn(t[tx][ty + j * 8]);
}

// softmax over s per (b,q) row; divide by column norm first; in place fp16
__global__ __launch_bounds__(256) void softmax_kernel(const int* __restrict__ smooth_ptr)
{
    float sm;
    {
        int iv = *smooth_ptr;
        if (iv >= -1000000 && iv <= 1000000) sm = (float)iv;
        else                                  sm = __int_as_float(iv);
    }
    const int w = threadIdx.x >> 5, lane = threadIdx.x & 31;
    const size_t row = (size_t)blockIdx.x * 8 + w;       // b*LQ + q
    const int b = (int)(row >> 9);
    __half* p = g_attn + row * LS;
    const float* cinv = g_cn + (size_t)b * LS;

    float v[32];
    float mx = -3.4e38f;
#pragma unroll
    for (int i = 0; i < 32; i++) {
        const int s = i * 32 + lane;
        v[i] = __half2float(p[s]) * cinv[s] * sm;
        mx = fmaxf(mx, v[i]);
    }
#pragma unroll
    for (int o = 16; o > 0; o >>= 1)
        mx = fmaxf(mx, __shfl_xor_sync(0xffffffffu, mx, o));
    float s = 0.f;
#pragma unroll
    for (int i = 0; i < 32; i++) {
        v[i] = __expf(v[i] - mx);
        s += v[i];
    }
#pragma unroll
    for (int o = 16; o > 0; o >>= 1)
        s += __shfl_xor_sync(0xffffffffu, s, o);
    const float inv = 1.f / s;
#pragma unroll
    for (int i = 0; i < 32; i++)
        p[i * 32 + lane] = __float2half_rn(v[i] * inv);
}

// wc (fp16): l2norm over D, diff = query - wc_norm, store fp16(diff^2)
__global__ __launch_bounds__(256) void diff2_kernel(const float* __restrict__ qry)
{
    __shared__ float red[8];
    const size_t row = blockIdx.x;
    __half2* wc = (__half2*)(g_wch + row * DD);
    const float* qp = qry + row * DD;
    const int tid = threadIdx.x, w = tid >> 5, lane = tid & 31;

    float2 v0 = __half22float2(wc[tid * 2]);
    float2 v1 = __half22float2(wc[tid * 2 + 1]);
    float ss = v0.x * v0.x + v0.y * v0.y + v1.x * v1.x + v1.y * v1.y;
#pragma unroll
    for (int o = 16; o > 0; o >>= 1)
        ss += __shfl_xor_sync(0xffffffffu, ss, o);
    if (lane == 0) red[w] = ss;
    __syncthreads();
    float tot = 0.f;
#pragma unroll
    for (int i = 0; i < 8; i++) tot += red[i];
    const float inv = 1.f / (sqrtf(tot) + EPSF);

    float4 q4 = ((const float4*)qp)[tid];
    const float d0 = q4.x - v0.x * inv, d1 = q4.y - v0.y * inv;
    const float d2 = q4.z - v1.x * inv, d3 = q4.w - v1.y * inv;
    wc[tid * 2]     = __floats2half2_rn(d0 * d0, d1 * d1);
    wc[tid * 2 + 1] = __floats2half2_rn(d2 * d2, d3 * d3);
}

// ---------------------------------------------------------------------------
extern "C" void kernel_launch(void* const* d_in, const int* in_sizes, int n_in,
                              void* d_out, int out_size)
{
    const float* qry  = (const float*)d_in[0];
    const float* ctx  = (const float*)d_in[1];
    const float* mat  = (const float*)d_in[2];
    const float* W    = (const float*)d_in[3];
    const float* bias = (const float*)d_in[4];
    const int*   smp  = (const int*)d_in[5];
    float* outp = (float*)d_out;

    __half *pqm, *pctxh, *pctxt, *pattn, *pwch, *pwh;
    float* pcn;
    cudaGetSymbolAddress((void**)&pqm,   g_qmh);
    cudaGetSymbolAddress((void**)&pctxh, g_ctxh);
    cudaGetSymbolAddress((void**)&pctxt, g_ctxt);
    cudaGetSymbolAddress((void**)&pattn, g_attn);
    cudaGetSymbolAddress((void**)&pwch,  g_wch);
    cudaGetSymbolAddress((void**)&pwh,   g_wh);
    cudaGetSymbolAddress((void**)&pcn,   g_cn);

    constexpr int SM01 = 3 * (128 + 128) * LDB32 * 4 + 512;   // 111104
    constexpr int SM2  = 3 * (64 + 256) * LDB32 * 4 + 256;    // 138496
    cudaFuncSetAttribute(hgemm<0>, cudaFuncAttributeMaxDynamicSharedMemorySize, SM01);
    cudaFuncSetAttribute(hgemm<1>, cudaFuncAttributeMaxDynamicSharedMemorySize, SM01);
    cudaFuncSetAttribute(hgemm<2>, cudaFuncAttributeMaxDynamicSharedMemorySize, SM2);

    prep_qm_kernel<<<(B_ * LQ * DD) / 4 / 256, 256>>>(qry, mat);
    prep_ctx_kernel<<<dim3(DD / 32, LS / 32, B_), 256>>>(ctx);
    prep_w_kernel<<<(SS * DD) / 4 / 256, 256>>>(W);
    zero_cn_kernel<<<(B_ * LS) / 256, 256>>>();

    // attn = lrelu(qm . ctx^T), fused column sumsq
    hgemm<0><<<dim3(LS / 128, LQ / 128, B_), 256, SM01>>>(
        pqm, pctxh, pattn, nullptr, pcn,
        DD, DD, LS, (size_t)LQ * DD, (size_t)LS * DD, (size_t)LQ * LS);

    inv_cn_kernel<<<(B_ * LS) / 256, 256>>>();
    softmax_kernel<<<B_ * LQ / 8, 256>>>(smp);

    // wc = attn . ctxT^T
    hgemm<1><<<dim3(DD / 128, LQ / 128, B_), 256, SM01>>>(
        pattn, pctxt, pwch, nullptr, nullptr,
        LS, LS, DD, (size_t)LQ * LS, (size_t)DD * LS, (size_t)LQ * DD);

    diff2_kernel<<<B_ * LQ, 256>>>(qry);

    // out = diff2 . W^T + b, fused l2norm over S
    hgemm<2><<<dim3(SS / 256, LQ / 64, B_), 256, SM2>>>(
        pwch, pwh, outp, bias, nullptr,
        DD, DD, SS, (size_t)LQ * DD, 0, (size_t)LQ * SS);
}